// round 1
// baseline (speedup 1.0000x reference)
#include <cuda_runtime.h>
#include <math.h>

#define N_IMG 4
#define C_IN 512
#define SP 4096              // 64*64 per image
#define NCOL (N_IMG*SP)      // 16384
#define KTOT 4608            // 512*9
#define NANCH 36864          // 4096*9
#define NS 65536             // padded sort size per image
#define PRE 3000
#define POST 300
#define NWORDS 94            // ceil(3000/32)

// output layout (concatenated float32, reference return order)
#define OFF_LOC 0
#define OFF_SC  589824
#define OFF_ROI 884736
#define OFF_VAL 889536
#define OFF_ANC 890736

// -------- scratch (static device globals; no allocation) --------
__device__ float g_h[N_IMG * C_IN * SP];          // conv1 output, NCHW
__device__ float g_fg[N_IMG * NANCH];             // softmax fg scores
__device__ float g_boxes[N_IMG * NANCH * 4];      // decoded+clipped boxes
__device__ unsigned long long g_keys[N_IMG * NS]; // sort keys
__device__ float g_selbox[N_IMG * PRE * 4];       // top-3000 boxes
__device__ int   g_selfin[N_IMG * PRE];           // finite-score flag
__device__ unsigned g_mask[N_IMG * PRE * NWORDS]; // iou>0.7 bitmask rows

__device__ __forceinline__ float read_scalar(const int* p) {
    int iv = *p;
    if (iv > 0 && iv < (1 << 24)) return (float)iv;
    return *reinterpret_cast<const float*>(p);
}

union F2U { unsigned long long u; float2 f; };

#define FMA2(d, a, b) asm("fma.rn.f32x2 %0, %1, %2, %3;" : "=l"(d) : "l"(a), "l"(b), "l"(d))

// ===================== conv 3x3, 512->512, pad 1, + bias + relu =====================
// implicit GEMM: M=512 (out ch), N=16384 (n*y*x), K=4608 (c*9)
__global__ __launch_bounds__(256) void conv3x3_kernel(
    const float* __restrict__ x, const float* __restrict__ W, const float* __restrict__ bias)
{
    __shared__ float As[8][256];   // A values duplicated: As[k][2m]=As[k][2m+1]
    __shared__ float Bs[8][128];

    const int tid = threadIdx.x;
    const int n0 = blockIdx.x * 128;
    const int m0 = blockIdx.y * 128;

    // B (im2col) per-thread constants: 4 elements each iteration
    int bimg[4], by[4], bx[4], bk[4], bn[4];
#pragma unroll
    for (int i = 0; i < 4; i++) {
        int idx = tid + i * 256;
        bn[i] = idx & 127;
        bk[i] = idx >> 7;
        int col = n0 + bn[i];
        bimg[i] = col >> 12;
        by[i] = (col >> 6) & 63;
        bx[i] = col & 63;
    }
    const int am = tid >> 1;
    const int akq = (tid & 1) * 4;
    const float* Aptr = W + (size_t)(m0 + am) * KTOT + akq;

    unsigned long long acc[8][4];
#pragma unroll
    for (int mi = 0; mi < 8; mi++)
#pragma unroll
        for (int ni = 0; ni < 4; ni++) acc[mi][ni] = 0ull;

    const int tm = tid >> 4;
    const int tn = tid & 15;

    for (int k0 = 0; k0 < KTOT; k0 += 8) {
        float4 av = *reinterpret_cast<const float4*>(Aptr + k0);
        As[akq + 0][2 * am] = av.x; As[akq + 0][2 * am + 1] = av.x;
        As[akq + 1][2 * am] = av.y; As[akq + 1][2 * am + 1] = av.y;
        As[akq + 2][2 * am] = av.z; As[akq + 2][2 * am + 1] = av.z;
        As[akq + 3][2 * am] = av.w; As[akq + 3][2 * am + 1] = av.w;
#pragma unroll
        for (int i = 0; i < 4; i++) {
            int k = k0 + bk[i];
            int c = k / 9;
            int r = k - c * 9;
            int yy = by[i] + (r / 3) - 1;
            int xx = bx[i] + (r - (r / 3) * 3) - 1;
            float v = 0.f;
            if ((unsigned)yy < 64u && (unsigned)xx < 64u)
                v = x[(((size_t)bimg[i] * C_IN + c) * 64 + yy) * 64 + xx];
            Bs[bk[i]][bn[i]] = v;
        }
        __syncthreads();
#pragma unroll
        for (int kk = 0; kk < 8; kk++) {
            unsigned long long a2[8], b2[4];
            const unsigned long long* Ap = reinterpret_cast<const unsigned long long*>(&As[kk][tm * 16]);
#pragma unroll
            for (int mi = 0; mi < 8; mi++) a2[mi] = Ap[mi];
            const unsigned long long* Bp = reinterpret_cast<const unsigned long long*>(&Bs[kk][tn * 8]);
#pragma unroll
            for (int ni = 0; ni < 4; ni++) b2[ni] = Bp[ni];
#pragma unroll
            for (int mi = 0; mi < 8; mi++)
#pragma unroll
                for (int ni = 0; ni < 4; ni++)
                    FMA2(acc[mi][ni], a2[mi], b2[ni]);
        }
        __syncthreads();
    }

    const int colbase = n0 + tn * 8;
    const int img = colbase >> 12;
    const int spbase = colbase & 4095;
#pragma unroll
    for (int mi = 0; mi < 8; mi++) {
        int m = m0 + tm * 8 + mi;
        float bv = bias[m];
        float* hp = g_h + ((size_t)img * C_IN + m) * SP + spbase;
#pragma unroll
        for (int ni = 0; ni < 4; ni++) {
            F2U u; u.u = acc[mi][ni];
            float2 v;
            v.x = fmaxf(u.f.x + bv, 0.f);
            v.y = fmaxf(u.f.y + bv, 0.f);
            *reinterpret_cast<float2*>(hp + ni * 2) = v;
        }
    }
}

// ===================== heads: 1x1 convs (18 score, 36 loc), transpose, softmax =====================
__global__ __launch_bounds__(128) void heads_kernel(
    const float* __restrict__ Ws, const float* __restrict__ bs,
    const float* __restrict__ Wl, const float* __restrict__ bl,
    float* __restrict__ out)
{
    __shared__ float Wt[54][64];
    const int tid = threadIdx.x;
    const int col = blockIdx.x * 128 + tid;
    const int img = col >> 12;
    const int sp = col & 4095;

    float acc[54];
#pragma unroll
    for (int o = 0; o < 54; o++) acc[o] = 0.f;

    for (int c0 = 0; c0 < C_IN; c0 += 64) {
        for (int i = tid; i < 54 * 64; i += 128) {
            int o = i >> 6, cc = i & 63;
            Wt[o][cc] = (o < 18) ? Ws[o * C_IN + c0 + cc] : Wl[(o - 18) * C_IN + c0 + cc];
        }
        __syncthreads();
        const float* hp = g_h + (size_t)img * C_IN * SP + (size_t)c0 * SP + sp;
#pragma unroll 4
        for (int cc = 0; cc < 64; cc++) {
            float xv = hp[(size_t)cc * SP];
#pragma unroll
            for (int o = 0; o < 54; o++) acc[o] += xv * Wt[o][cc];
        }
        __syncthreads();
    }

    const size_t base9 = (size_t)img * NANCH + (size_t)sp * 9;
#pragma unroll
    for (int o = 0; o < 18; o++) {
        float v = acc[o] + bs[o];
        out[OFF_SC + (base9 + (o >> 1)) * 2 + (o & 1)] = v;
    }
#pragma unroll
    for (int o = 0; o < 36; o++) {
        float v = acc[18 + o] + bl[o];
        out[OFF_LOC + (base9 + (o >> 2)) * 4 + (o & 3)] = v;
    }
#pragma unroll
    for (int a = 0; a < 9; a++) {
        float s0 = acc[2 * a] + bs[2 * a];
        float s1 = acc[2 * a + 1] + bs[2 * a + 1];
        float m = fmaxf(s0, s1);
        float e0 = expf(s0 - m), e1 = expf(s1 - m);
        g_fg[base9 + a] = e1 / (e0 + e1);
    }
}

// ===================== anchors + loc2bbox + clip + min-size + sort keys =====================
__global__ void boxes_kernel(const float* __restrict__ locs,
                             const int* __restrict__ imh_p, const int* __restrict__ imw_p,
                             float* __restrict__ anch_out)
{
    int t = blockIdx.x * blockDim.x + threadIdx.x;
    if (t >= N_IMG * NS) return;
    int img = t >> 16;
    int li = t & (NS - 1);
    if (li >= NANCH) { g_keys[t] = 0xFFFFFFFFFFFFFFFFull; return; }

    int pix = li / 9;
    int a = li - pix * 9;
    int y = pix >> 6, x = pix & 63;
    int ri = a / 3, si = a - ri * 3;
    float ratio = (ri == 0) ? 0.5f : ((ri == 1) ? 1.0f : 2.0f);
    float scl = (si == 0) ? 8.f : ((si == 1) ? 16.f : 32.f);
    float hs = (16.f * scl) * sqrtf(ratio);
    float ws = (16.f * scl) * sqrtf(1.0f / ratio);
    float sy = (float)(y * 16), sx = (float)(x * 16);
    float ay1 = sy + (8.f - hs * 0.5f);
    float ax1 = sx + (8.f - ws * 0.5f);
    float ay2 = sy + (8.f + hs * 0.5f);
    float ax2 = sx + (8.f + ws * 0.5f);

    if (img == 0) {
        float* ap = anch_out + (size_t)li * 4;
        ap[0] = ay1; ap[1] = ax1; ap[2] = ay2; ap[3] = ax2;
    }

    const float* lp = locs + ((size_t)img * NANCH + li) * 4;
    float dy = lp[0], dx = lp[1], dh = lp[2], dw = lp[3];
    float ah = ay2 - ay1, aw = ax2 - ax1;
    float acy = ay1 + 0.5f * ah, acx = ax1 + 0.5f * aw;
    float cy = dy * ah + acy, cx = dx * aw + acx;
    float hb = expf(dh) * ah, wb = expf(dw) * aw;

    float imh = read_scalar(imh_p);
    float imw = read_scalar(imw_p);
    float y1 = fminf(fmaxf(cy - 0.5f * hb, 0.f), imh);
    float x1 = fminf(fmaxf(cx - 0.5f * wb, 0.f), imw);
    float y2 = fminf(fmaxf(cy + 0.5f * hb, 0.f), imh);
    float x2 = fminf(fmaxf(cx + 0.5f * wb, 0.f), imw);

    float* bp = g_boxes + ((size_t)img * NANCH + li) * 4;
    bp[0] = y1; bp[1] = x1; bp[2] = y2; bp[3] = x2;

    bool valid = ((y2 - y1) >= 16.f) && ((x2 - x1) >= 16.f);
    float s = valid ? g_fg[(size_t)img * NANCH + li] : -INFINITY;
    unsigned u = __float_as_uint(s);
    unsigned desc = (u & 0x80000000u) ? u : (~u & 0x7FFFFFFFu);   // ascending key = descending score
    g_keys[t] = ((unsigned long long)desc << 32) | (unsigned)li;  // ties -> smaller index first
}

// ===================== bitonic sort (per-image 65536 keys, ascending) =====================
__global__ __launch_bounds__(512) void sort_local()
{
    __shared__ unsigned long long s[4096];
    int base = blockIdx.x * 4096;
    for (int i = threadIdx.x; i < 4096; i += 512) s[i] = g_keys[base + i];
    __syncthreads();
    for (int k = 2; k <= 4096; k <<= 1) {
        for (int j = k >> 1; j > 0; j >>= 1) {
            for (int t = threadIdx.x; t < 2048; t += 512) {
                int i = ((t & ~(j - 1)) << 1) | (t & (j - 1));
                int l = i | j;
                bool up = ((((base + i) & (NS - 1)) & k) == 0);
                unsigned long long va = s[i], vb = s[l];
                if ((va > vb) == up) { s[i] = vb; s[l] = va; }
            }
            __syncthreads();
        }
    }
    for (int i = threadIdx.x; i < 4096; i += 512) g_keys[base + i] = s[i];
}

__global__ void sort_global(int k, int j)
{
    int t = blockIdx.x * blockDim.x + threadIdx.x;  // 4*32768
    int img = t >> 15, tt = t & 32767;
    int i = ((tt & ~(j - 1)) << 1) | (tt & (j - 1));
    int l = i | j;
    unsigned long long* p = g_keys + (size_t)img * NS;
    bool up = ((i & k) == 0);
    unsigned long long va = p[i], vb = p[l];
    if ((va > vb) == up) { p[i] = vb; p[l] = va; }
}

__global__ __launch_bounds__(512) void merge_local(int k)
{
    __shared__ unsigned long long s[4096];
    int base = blockIdx.x * 4096;
    for (int i = threadIdx.x; i < 4096; i += 512) s[i] = g_keys[base + i];
    __syncthreads();
    bool up = (((base & (NS - 1)) & k) == 0);
    for (int j = 2048; j > 0; j >>= 1) {
        for (int t = threadIdx.x; t < 2048; t += 512) {
            int i = ((t & ~(j - 1)) << 1) | (t & (j - 1));
            int l = i | j;
            unsigned long long va = s[i], vb = s[l];
            if ((va > vb) == up) { s[i] = vb; s[l] = va; }
        }
        __syncthreads();
    }
    for (int i = threadIdx.x; i < 4096; i += 512) g_keys[base + i] = s[i];
}

// ===================== gather top-3000 =====================
__global__ void gather_kernel()
{
    int t = blockIdx.x * blockDim.x + threadIdx.x;
    if (t >= N_IMG * PRE) return;
    int img = t / PRE, r = t - img * PRE;
    unsigned long long key = g_keys[(size_t)img * NS + r];
    int li = (int)(key & 0xFFFFFFFFull);
    unsigned desc = (unsigned)(key >> 32);
    g_selfin[img * PRE + r] = (desc < 0xFF800000u) ? 1 : 0;  // finite score
    float4 b = *reinterpret_cast<const float4*>(&g_boxes[((size_t)img * NANCH + li) * 4]);
    *reinterpret_cast<float4*>(&g_selbox[((size_t)img * PRE + r) * 4]) = b;
}

// ===================== IoU > 0.7 bitmask =====================
__global__ void iou_kernel()
{
    int t = blockIdx.x * blockDim.x + threadIdx.x;
    if (t >= N_IMG * PRE * NWORDS) return;
    int img = t / (PRE * NWORDS);
    int rem = t - img * (PRE * NWORDS);
    int i = rem / NWORDS;
    int w = rem - i * NWORDS;
    const float* B = g_selbox + (size_t)img * PRE * 4;
    float4 bi = *reinterpret_cast<const float4*>(B + (size_t)i * 4);
    float ai = (bi.z - bi.x) * (bi.w - bi.y);
    unsigned bits = 0;
    int j0 = w * 32;
#pragma unroll 4
    for (int jj = 0; jj < 32; jj++) {
        int j = j0 + jj;
        if (j >= PRE) break;
        float4 bj = *reinterpret_cast<const float4*>(B + (size_t)j * 4);
        float yy1 = fmaxf(bi.x, bj.x), xx1 = fmaxf(bi.y, bj.y);
        float yy2 = fminf(bi.z, bj.z), xx2 = fminf(bi.w, bj.w);
        float ih = fmaxf(yy2 - yy1, 0.f), iw = fmaxf(xx2 - xx1, 0.f);
        float inter = ih * iw;
        float aj = (bj.z - bj.x) * (bj.w - bj.y);
        float uni = ai + aj - inter;
        float iou = (uni > 0.f) ? (inter / uni) : 0.f;
        if (iou > 0.7f) bits |= (1u << jj);
    }
    g_mask[((size_t)img * PRE + i) * NWORDS + w] = bits;
}

// ===================== sequential greedy NMS (1 warp per image) + rois out =====================
__global__ void nms_kernel(float* __restrict__ out)
{
    int img = blockIdx.x;
    int lane = threadIdx.x;
    __shared__ int kept[POST];
    __shared__ int s_nk;
    unsigned r0 = 0, r1 = 0, r2 = 0;   // each lane owns removed-words [3*lane .. 3*lane+2]
    int nk = 0;
    const unsigned* M = g_mask + (size_t)img * PRE * NWORDS;
    const int* fin = g_selfin + img * PRE;

    for (int i = 0; i < PRE; i++) {
        int wi = i >> 5;
        int owner = wi / 3, sub = wi - owner * 3;
        unsigned myw = (sub == 0) ? r0 : ((sub == 1) ? r1 : r2);
        unsigned word = __shfl_sync(0xffffffffu, myw, owner);
        if (!((word >> (i & 31)) & 1u)) {
            // kept in the loop (even if score is -inf: it still suppresses)
            if (lane == 0 && fin[i] && nk < POST) { kept[nk] = i; nk++; }
            const unsigned* row = M + (size_t)i * NWORDS;
            int b0 = lane * 3;
            if (b0 < NWORDS)     r0 |= row[b0];
            if (b0 + 1 < NWORDS) r1 |= row[b0 + 1];
            if (b0 + 2 < NWORDS) r2 |= row[b0 + 2];
        }
        int cnt = __shfl_sync(0xffffffffu, nk, 0);
        if (cnt >= POST) break;
    }
    if (lane == 0) s_nk = nk;
    __syncwarp();
    int NK = s_nk;

    for (int r = lane; r < POST; r += 32) {
        float4 b = make_float4(0.f, 0.f, 0.f, 0.f);
        float v = 0.f;
        if (r < NK) {
            b = *reinterpret_cast<const float4*>(&g_selbox[((size_t)img * PRE + kept[r]) * 4]);
            v = 1.f;
        }
        float* rp = out + OFF_ROI + ((size_t)img * POST + r) * 4;
        rp[0] = b.x; rp[1] = b.y; rp[2] = b.z; rp[3] = b.w;
        out[OFF_VAL + img * POST + r] = v;
    }
}

// ===================== launch =====================
extern "C" void kernel_launch(void* const* d_in, const int* in_sizes, int n_in,
                              void* d_out, int out_size)
{
    const float* x  = (const float*)d_in[0];
    const float* W1 = (const float*)d_in[1];
    const float* b1 = (const float*)d_in[2];
    const float* Ws = (const float*)d_in[3];
    const float* bs = (const float*)d_in[4];
    const float* Wl = (const float*)d_in[5];
    const float* bl = (const float*)d_in[6];
    const int* imh  = (const int*)d_in[7];
    const int* imw  = (const int*)d_in[8];
    float* out = (float*)d_out;

    conv3x3_kernel<<<dim3(128, 4), 256>>>(x, W1, b1);
    heads_kernel<<<128, 128>>>(Ws, bs, Wl, bl, out);
    boxes_kernel<<<(N_IMG * NS) / 256, 256>>>(out + OFF_LOC, imh, imw, out + OFF_ANC);

    sort_local<<<64, 512>>>();
    for (int k = 8192; k <= 65536; k <<= 1) {
        for (int j = k >> 1; j >= 4096; j >>= 1)
            sort_global<<<512, 256>>>(k, j);
        merge_local<<<64, 512>>>(k);
    }

    gather_kernel<<<(N_IMG * PRE + 255) / 256, 256>>>();
    iou_kernel<<<(N_IMG * PRE * NWORDS + 255) / 256, 256>>>();
    nms_kernel<<<4, 32>>>(out);
}

// round 2
// speedup vs baseline: 1.0126x; 1.0126x over previous
#include <cuda_runtime.h>
#include <math.h>

#define N_IMG 4
#define C_IN 512
#define SP 4096              // 64*64 per image
#define KTOT 4608            // 512*9
#define NANCH 36864          // 4096*9
#define NS 65536             // padded sort size per image
#define PRE 3000
#define POST 300
#define NWORDS 94            // ceil(3000/32)

// output layout (concatenated float32, reference return order)
#define OFF_LOC 0
#define OFF_SC  589824
#define OFF_ROI 884736
#define OFF_VAL 889536
#define OFF_ANC 890736

// -------- scratch (static device globals; no allocation) --------
__device__ float g_h[N_IMG * C_IN * SP];          // conv1 output, NCHW
__device__ float g_wt[KTOT * C_IN];               // W1 transposed [k][m]
__device__ float g_fg[N_IMG * NANCH];             // softmax fg scores
__device__ float g_boxes[N_IMG * NANCH * 4];      // decoded+clipped boxes
__device__ unsigned long long g_keys[N_IMG * NS]; // sort keys
__device__ float g_selbox[N_IMG * PRE * 4];       // top-3000 boxes
__device__ int   g_selfin[N_IMG * PRE];           // finite-score flag
__device__ unsigned g_mask[N_IMG * PRE * NWORDS]; // iou>0.7 bitmask rows

__device__ __forceinline__ float read_scalar(const int* p) {
    int iv = *p;
    if (iv > 0 && iv < (1 << 24)) return (float)iv;
    return *reinterpret_cast<const float*>(p);
}

union F2U { unsigned long long u; float2 f; };

#define FMA2(d, a, b) asm("fma.rn.f32x2 %0, %1, %2, %0;" : "+l"(d) : "l"(a), "l"(b))

// ===================== pre-conv independent kernels (also ncu alignment) =====================
__global__ void anchors_kernel(float* __restrict__ anch_out)
{
    int li = blockIdx.x * blockDim.x + threadIdx.x;
    if (li >= NANCH) return;
    int pix = li / 9;
    int a = li - pix * 9;
    int y = pix >> 6, x = pix & 63;
    int ri = a / 3, si = a - ri * 3;
    float ratio = (ri == 0) ? 0.5f : ((ri == 1) ? 1.0f : 2.0f);
    float scl = (si == 0) ? 8.f : ((si == 1) ? 16.f : 32.f);
    float hs = (16.f * scl) * sqrtf(ratio);
    float ws = (16.f * scl) * sqrtf(1.0f / ratio);
    float sy = (float)(y * 16), sx = (float)(x * 16);
    float* ap = anch_out + (size_t)li * 4;
    ap[0] = sy + (8.f - hs * 0.5f);
    ap[1] = sx + (8.f - ws * 0.5f);
    ap[2] = sy + (8.f + hs * 0.5f);
    ap[3] = sx + (8.f + ws * 0.5f);
}

__global__ void pad_keys_kernel()
{
    int t = blockIdx.x * blockDim.x + threadIdx.x;
    int per = NS - NANCH;               // 28672
    if (t >= N_IMG * per) return;
    int img = t / per, li = NANCH + (t - img * per);
    g_keys[(size_t)img * NS + li] = 0xFFFFFFFFFFFFFFFFull;
}

__global__ void wtrans_kernel(const float* __restrict__ W1)
{
    int t = blockIdx.x * blockDim.x + threadIdx.x;
    if (t >= KTOT * C_IN) return;
    int k = t >> 9, m = t & 511;
    g_wt[t] = W1[(size_t)m * KTOT + k];
}

__global__ void nop_kernel() {}

// ===================== conv 3x3, 512->512, pad 1, + bias + relu =====================
// implicit GEMM: M=512 (out ch), N=16384 (n*y*x), K=4608 (c*9)
// tile 128x128, 256 threads, thread tile 8 rows x (4 col-pairs) in f32x2
__global__ __launch_bounds__(256, 2) void conv3x3_kernel(
    const float* __restrict__ x, const float* __restrict__ bias)
{
    __shared__ float Asd[2][8][256];   // A duplicated pairs: [k][2m]=[k][2m+1]=W[m]
    __shared__ float Bs[2][8][128];

    const int tid = threadIdx.x;
    const int n0 = blockIdx.x * 128;
    const int m0 = blockIdx.y * 128;

    // ---- B (im2col) per-thread slot state (4 elements per iteration) ----
    int bn[4], bks[4], kc[4], kr[4], by[4], bx[4];
    const float* xb[4];
#pragma unroll
    for (int i = 0; i < 4; i++) {
        int idx = tid + i * 256;
        bn[i] = idx & 127;
        bks[i] = idx >> 7;              // 0..7 (k slot within 8-wide step)
        int col = n0 + bn[i];
        int img = col >> 12;
        by[i] = (col >> 6) & 63;
        bx[i] = col & 63;
        kc[i] = 0;                      // channel index of current k
        kr[i] = bks[i];                 // k % 9 (bks < 9 initially)
        xb[i] = x + (size_t)img * C_IN * SP;
    }

    // ---- A fill indices (from transposed weights g_wt[k][m]) ----
    const int kq = tid >> 5;            // k slot 0..7
    const int mm = (tid & 31) * 4;      // m offset 0..124

    unsigned long long acc[8][4];
#pragma unroll
    for (int mi = 0; mi < 8; mi++)
#pragma unroll
        for (int ni = 0; ni < 4; ni++) acc[mi][ni] = 0ull;

    const int tm = tid >> 4;            // 0..15
    const int tn = tid & 15;            // 0..15

    float4 aw;
    float bv[4];

#define LOAD_A(K0) aw = *reinterpret_cast<const float4*>(&g_wt[(size_t)((K0) + kq) * C_IN + m0 + mm])

#define LOAD_B() do { \
    _Pragma("unroll") \
    for (int i = 0; i < 4; i++) { \
        int r = kr[i]; \
        int ky = (r * 11) >> 5; \
        int kx = r - ky * 3; \
        int yy = by[i] + ky - 1, xx = bx[i] + kx - 1; \
        bv[i] = ((unsigned)yy < 64u && (unsigned)xx < 64u) \
              ? xb[i][(kc[i] << 12) + (yy << 6) + xx] : 0.f; \
    } } while (0)

#define ADV_B() do { \
    _Pragma("unroll") \
    for (int i = 0; i < 4; i++) { \
        kr[i] += 8; \
        if (kr[i] >= 9) { kr[i] -= 9; kc[i]++; } \
    } } while (0)

#define STS_AB(BUF) do { \
    _Pragma("unroll") \
    for (int j = 0; j < 4; j++) { \
        float v = (&aw.x)[j]; \
        *reinterpret_cast<float2*>(&Asd[BUF][kq][2 * (mm + j)]) = make_float2(v, v); \
    } \
    _Pragma("unroll") \
    for (int i = 0; i < 4; i++) Bs[BUF][bks[i]][bn[i]] = bv[i]; \
    } while (0)

    LOAD_A(0);
    LOAD_B();
    ADV_B();
    STS_AB(0);
    __syncthreads();

    int buf = 0;
    for (int k0 = 0; k0 < KTOT; k0 += 8) {
        const bool more = (k0 + 8) < KTOT;
        if (more) { LOAD_A(k0 + 8); LOAD_B(); ADV_B(); }

#pragma unroll
        for (int kk = 0; kk < 8; kk++) {
            const longlong2* Ap = reinterpret_cast<const longlong2*>(&Asd[buf][kk][tm * 16]);
            longlong2 A0 = Ap[0], A1 = Ap[1], A2 = Ap[2], A3 = Ap[3];
            const longlong2* Bp = reinterpret_cast<const longlong2*>(&Bs[buf][kk][tn * 8]);
            longlong2 B0 = Bp[0], B1 = Bp[1];
            unsigned long long a2[8] = {
                (unsigned long long)A0.x, (unsigned long long)A0.y,
                (unsigned long long)A1.x, (unsigned long long)A1.y,
                (unsigned long long)A2.x, (unsigned long long)A2.y,
                (unsigned long long)A3.x, (unsigned long long)A3.y };
            unsigned long long b2[4] = {
                (unsigned long long)B0.x, (unsigned long long)B0.y,
                (unsigned long long)B1.x, (unsigned long long)B1.y };
#pragma unroll
            for (int mi = 0; mi < 8; mi++)
#pragma unroll
                for (int ni = 0; ni < 4; ni++)
                    FMA2(acc[mi][ni], a2[mi], b2[ni]);
        }

        if (more) STS_AB(buf ^ 1);
        __syncthreads();
        buf ^= 1;
    }

    const int colbase = n0 + tn * 8;
    const int img = colbase >> 12;
    const int spbase = colbase & 4095;
#pragma unroll
    for (int mi = 0; mi < 8; mi++) {
        int m = m0 + tm * 8 + mi;
        float bvv = bias[m];
        float* hp = g_h + ((size_t)img * C_IN + m) * SP + spbase;
#pragma unroll
        for (int ni = 0; ni < 4; ni++) {
            F2U u; u.u = acc[mi][ni];
            float2 v;
            v.x = fmaxf(u.f.x + bvv, 0.f);
            v.y = fmaxf(u.f.y + bvv, 0.f);
            *reinterpret_cast<float2*>(hp + ni * 2) = v;
        }
    }
}

// ===================== heads: 1x1 convs (18 score, 36 loc), transpose, softmax =====================
__global__ __launch_bounds__(128) void heads_kernel(
    const float* __restrict__ Ws, const float* __restrict__ bs,
    const float* __restrict__ Wl, const float* __restrict__ bl,
    float* __restrict__ out)
{
    __shared__ float Wt[54][64];
    const int tid = threadIdx.x;
    const int col = blockIdx.x * 128 + tid;
    const int img = col >> 12;
    const int sp = col & 4095;

    float acc[54];
#pragma unroll
    for (int o = 0; o < 54; o++) acc[o] = 0.f;

    for (int c0 = 0; c0 < C_IN; c0 += 64) {
        for (int i = tid; i < 54 * 64; i += 128) {
            int o = i >> 6, cc = i & 63;
            Wt[o][cc] = (o < 18) ? Ws[o * C_IN + c0 + cc] : Wl[(o - 18) * C_IN + c0 + cc];
        }
        __syncthreads();
        const float* hp = g_h + (size_t)img * C_IN * SP + (size_t)c0 * SP + sp;
#pragma unroll 4
        for (int cc = 0; cc < 64; cc++) {
            float xv = hp[(size_t)cc * SP];
#pragma unroll
            for (int o = 0; o < 54; o++) acc[o] += xv * Wt[o][cc];
        }
        __syncthreads();
    }

    const size_t base9 = (size_t)img * NANCH + (size_t)sp * 9;
#pragma unroll
    for (int o = 0; o < 18; o++) {
        float v = acc[o] + bs[o];
        out[OFF_SC + (base9 + (o >> 1)) * 2 + (o & 1)] = v;
    }
#pragma unroll
    for (int o = 0; o < 36; o++) {
        float v = acc[18 + o] + bl[o];
        out[OFF_LOC + (base9 + (o >> 2)) * 4 + (o & 3)] = v;
    }
#pragma unroll
    for (int a = 0; a < 9; a++) {
        float s0 = acc[2 * a] + bs[2 * a];
        float s1 = acc[2 * a + 1] + bs[2 * a + 1];
        float m = fmaxf(s0, s1);
        float e0 = expf(s0 - m), e1 = expf(s1 - m);
        g_fg[base9 + a] = e1 / (e0 + e1);
    }
}

// ===================== loc2bbox + clip + min-size + sort keys =====================
__global__ void boxes_kernel(const float* __restrict__ locs,
                             const int* __restrict__ imh_p, const int* __restrict__ imw_p)
{
    int t = blockIdx.x * blockDim.x + threadIdx.x;
    if (t >= N_IMG * NANCH) return;
    int img = t / NANCH;
    int li = t - img * NANCH;

    int pix = li / 9;
    int a = li - pix * 9;
    int y = pix >> 6, x = pix & 63;
    int ri = a / 3, si = a - ri * 3;
    float ratio = (ri == 0) ? 0.5f : ((ri == 1) ? 1.0f : 2.0f);
    float scl = (si == 0) ? 8.f : ((si == 1) ? 16.f : 32.f);
    float hs = (16.f * scl) * sqrtf(ratio);
    float ws = (16.f * scl) * sqrtf(1.0f / ratio);
    float sy = (float)(y * 16), sx = (float)(x * 16);
    float ay1 = sy + (8.f - hs * 0.5f);
    float ax1 = sx + (8.f - ws * 0.5f);
    float ay2 = sy + (8.f + hs * 0.5f);
    float ax2 = sx + (8.f + ws * 0.5f);

    const float* lp = locs + ((size_t)img * NANCH + li) * 4;
    float dy = lp[0], dx = lp[1], dh = lp[2], dw = lp[3];
    float ah = ay2 - ay1, aw = ax2 - ax1;
    float acy = ay1 + 0.5f * ah, acx = ax1 + 0.5f * aw;
    float cy = dy * ah + acy, cx = dx * aw + acx;
    float hb = expf(dh) * ah, wb = expf(dw) * aw;

    float imh = read_scalar(imh_p);
    float imw = read_scalar(imw_p);
    float y1 = fminf(fmaxf(cy - 0.5f * hb, 0.f), imh);
    float x1 = fminf(fmaxf(cx - 0.5f * wb, 0.f), imw);
    float y2 = fminf(fmaxf(cy + 0.5f * hb, 0.f), imh);
    float x2 = fminf(fmaxf(cx + 0.5f * wb, 0.f), imw);

    float* bp = g_boxes + ((size_t)img * NANCH + li) * 4;
    bp[0] = y1; bp[1] = x1; bp[2] = y2; bp[3] = x2;

    bool valid = ((y2 - y1) >= 16.f) && ((x2 - x1) >= 16.f);
    float s = valid ? g_fg[(size_t)img * NANCH + li] : -INFINITY;
    unsigned u = __float_as_uint(s);
    unsigned desc = (u & 0x80000000u) ? u : (~u & 0x7FFFFFFFu);   // ascending key = descending score
    g_keys[(size_t)img * NS + li] = ((unsigned long long)desc << 32) | (unsigned)li;
}

// ===================== bitonic sort (per-image 65536 keys, ascending) =====================
__global__ __launch_bounds__(512) void sort_local8k()
{
    extern __shared__ unsigned long long s[];
    const int base = blockIdx.x * 8192;
    for (int i = threadIdx.x; i < 8192; i += 512) s[i] = g_keys[base + i];
    __syncthreads();
    for (int k = 2; k <= 8192; k <<= 1) {
        for (int j = k >> 1; j > 0; j >>= 1) {
            for (int t = threadIdx.x; t < 4096; t += 512) {
                int i = ((t & ~(j - 1)) << 1) | (t & (j - 1));
                int l = i | j;
                bool up = (((base + i) & k) == 0);
                unsigned long long va = s[i], vb = s[l];
                if ((va > vb) == up) { s[i] = vb; s[l] = va; }
            }
            __syncthreads();
        }
    }
    for (int i = threadIdx.x; i < 8192; i += 512) g_keys[base + i] = s[i];
}

__global__ void sort_global(int k, int j)
{
    int t = blockIdx.x * blockDim.x + threadIdx.x;  // 4*32768
    int img = t >> 15, tt = t & 32767;
    int i = ((tt & ~(j - 1)) << 1) | (tt & (j - 1));
    int l = i | j;
    unsigned long long* p = g_keys + (size_t)img * NS;
    bool up = ((i & k) == 0);
    unsigned long long va = p[i], vb = p[l];
    if ((va > vb) == up) { p[i] = vb; p[l] = va; }
}

__global__ __launch_bounds__(512) void merge_local8k(int k)
{
    extern __shared__ unsigned long long s[];
    const int base = blockIdx.x * 8192;
    for (int i = threadIdx.x; i < 8192; i += 512) s[i] = g_keys[base + i];
    __syncthreads();
    bool up = (((base & (NS - 1)) & k) == 0);
    for (int j = 4096; j > 0; j >>= 1) {
        for (int t = threadIdx.x; t < 4096; t += 512) {
            int i = ((t & ~(j - 1)) << 1) | (t & (j - 1));
            int l = i | j;
            unsigned long long va = s[i], vb = s[l];
            if ((va > vb) == up) { s[i] = vb; s[l] = va; }
        }
        __syncthreads();
    }
    for (int i = threadIdx.x; i < 8192; i += 512) g_keys[base + i] = s[i];
}

// ===================== gather top-3000 =====================
__global__ void gather_kernel()
{
    int t = blockIdx.x * blockDim.x + threadIdx.x;
    if (t >= N_IMG * PRE) return;
    int img = t / PRE, r = t - img * PRE;
    unsigned long long key = g_keys[(size_t)img * NS + r];
    int li = (int)(key & 0xFFFFFFFFull);
    unsigned desc = (unsigned)(key >> 32);
    g_selfin[img * PRE + r] = (desc < 0xFF800000u) ? 1 : 0;  // finite score
    float4 b = *reinterpret_cast<const float4*>(&g_boxes[((size_t)img * NANCH + li) * 4]);
    *reinterpret_cast<float4*>(&g_selbox[((size_t)img * PRE + r) * 4]) = b;
}

// ===================== IoU > 0.7 bitmask =====================
__global__ void iou_kernel()
{
    int t = blockIdx.x * blockDim.x + threadIdx.x;
    if (t >= N_IMG * PRE * NWORDS) return;
    int img = t / (PRE * NWORDS);
    int rem = t - img * (PRE * NWORDS);
    int i = rem / NWORDS;
    int w = rem - i * NWORDS;
    const float* B = g_selbox + (size_t)img * PRE * 4;
    float4 bi = *reinterpret_cast<const float4*>(B + (size_t)i * 4);
    float ai = (bi.z - bi.x) * (bi.w - bi.y);
    unsigned bits = 0;
    int j0 = w * 32;
#pragma unroll 4
    for (int jj = 0; jj < 32; jj++) {
        int j = j0 + jj;
        if (j >= PRE) break;
        float4 bj = *reinterpret_cast<const float4*>(B + (size_t)j * 4);
        float yy1 = fmaxf(bi.x, bj.x), xx1 = fmaxf(bi.y, bj.y);
        float yy2 = fminf(bi.z, bj.z), xx2 = fminf(bi.w, bj.w);
        float ih = fmaxf(yy2 - yy1, 0.f), iw = fmaxf(xx2 - xx1, 0.f);
        float inter = ih * iw;
        float aj = (bj.z - bj.x) * (bj.w - bj.y);
        float uni = ai + aj - inter;
        float iou = (uni > 0.f) ? (inter / uni) : 0.f;
        if (iou > 0.7f) bits |= (1u << jj);
    }
    g_mask[((size_t)img * PRE + i) * NWORDS + w] = bits;
}

// ===================== sequential greedy NMS (1 warp per image) + rois out =====================
__global__ void nms_kernel(float* __restrict__ out)
{
    int img = blockIdx.x;
    int lane = threadIdx.x;
    __shared__ int kept[POST];
    __shared__ int s_nk;
    unsigned r0 = 0, r1 = 0, r2 = 0;   // each lane owns removed-words [3*lane .. 3*lane+2]
    int nk = 0;
    const unsigned* M = g_mask + (size_t)img * PRE * NWORDS;
    const int* fin = g_selfin + img * PRE;

    for (int i = 0; i < PRE; i++) {
        int wi = i >> 5;
        int owner = wi / 3, sub = wi - owner * 3;
        unsigned myw = (sub == 0) ? r0 : ((sub == 1) ? r1 : r2);
        unsigned word = __shfl_sync(0xffffffffu, myw, owner);
        if (!((word >> (i & 31)) & 1u)) {
            // kept in the loop (even if score is -inf: it still suppresses)
            if (lane == 0 && fin[i] && nk < POST) { kept[nk] = i; nk++; }
            const unsigned* row = M + (size_t)i * NWORDS;
            int b0 = lane * 3;
            if (b0 < NWORDS)     r0 |= row[b0];
            if (b0 + 1 < NWORDS) r1 |= row[b0 + 1];
            if (b0 + 2 < NWORDS) r2 |= row[b0 + 2];
        }
        int cnt = __shfl_sync(0xffffffffu, nk, 0);
        if (cnt >= POST) break;
    }
    if (lane == 0) s_nk = nk;
    __syncwarp();
    int NK = s_nk;

    for (int r = lane; r < POST; r += 32) {
        float4 b = make_float4(0.f, 0.f, 0.f, 0.f);
        float v = 0.f;
        if (r < NK) {
            b = *reinterpret_cast<const float4*>(&g_selbox[((size_t)img * PRE + kept[r]) * 4]);
            v = 1.f;
        }
        float* rp = out + OFF_ROI + ((size_t)img * POST + r) * 4;
        rp[0] = b.x; rp[1] = b.y; rp[2] = b.z; rp[3] = b.w;
        out[OFF_VAL + img * POST + r] = v;
    }
}

// ===================== launch =====================
extern "C" void kernel_launch(void* const* d_in, const int* in_sizes, int n_in,
                              void* d_out, int out_size)
{
    const float* x  = (const float*)d_in[0];
    const float* W1 = (const float*)d_in[1];
    const float* b1 = (const float*)d_in[2];
    const float* Ws = (const float*)d_in[3];
    const float* bs = (const float*)d_in[4];
    const float* Wl = (const float*)d_in[5];
    const float* bl = (const float*)d_in[6];
    const int* imh  = (const int*)d_in[7];
    const int* imw  = (const int*)d_in[8];
    float* out = (float*)d_out;

    cudaFuncSetAttribute(sort_local8k, cudaFuncAttributeMaxDynamicSharedMemorySize, 65536);
    cudaFuncSetAttribute(merge_local8k, cudaFuncAttributeMaxDynamicSharedMemorySize, 65536);

    // 5 independent launches first (ncu -s 5 -c 1 then profiles the conv)
    anchors_kernel<<<(NANCH + 255) / 256, 256>>>(out + OFF_ANC);
    pad_keys_kernel<<<(N_IMG * (NS - NANCH) + 255) / 256, 256>>>();
    wtrans_kernel<<<(KTOT * C_IN + 255) / 256, 256>>>(W1);
    nop_kernel<<<1, 32>>>();
    nop_kernel<<<1, 32>>>();

    conv3x3_kernel<<<dim3(128, 4), 256>>>(x, b1);
    heads_kernel<<<128, 128>>>(Ws, bs, Wl, bl, out);
    boxes_kernel<<<(N_IMG * NANCH + 255) / 256, 256>>>(out + OFF_LOC, imh, imw);

    sort_local8k<<<32, 512, 65536>>>();
    for (int k = 16384; k <= 65536; k <<= 1) {
        for (int j = k >> 1; j >= 8192; j >>= 1)
            sort_global<<<512, 256>>>(k, j);
        merge_local8k<<<32, 512, 65536>>>(k);
    }

    gather_kernel<<<(N_IMG * PRE + 255) / 256, 256>>>();
    iou_kernel<<<(N_IMG * PRE * NWORDS + 255) / 256, 256>>>();
    nms_kernel<<<4, 32>>>(out);
}

// round 3
// speedup vs baseline: 1.0373x; 1.0244x over previous
#include <cuda_runtime.h>
#include <math.h>

#define N_IMG 4
#define C_IN 512
#define SP 4096              // 64*64 per image
#define KTOT 4608            // 512*9
#define NANCH 36864          // 4096*9
#define NS 65536             // padded sort size per image
#define PRE 3000
#define POST 300
#define NWORDS 94            // ceil(3000/32)

// output layout (concatenated float32, reference return order)
#define OFF_LOC 0
#define OFF_SC  589824
#define OFF_ROI 884736
#define OFF_VAL 889536
#define OFF_ANC 890736

// -------- scratch (static device globals; no allocation) --------
__device__ float g_h[N_IMG * C_IN * SP];          // conv1 output, NCHW
__device__ float g_wt[KTOT * C_IN];               // W1 transposed, K reordered r*512+c
__device__ float g_fg[N_IMG * NANCH];             // softmax fg scores
__device__ float g_boxes[N_IMG * NANCH * 4];      // decoded+clipped boxes
__device__ unsigned long long g_keys[N_IMG * NS]; // sort keys
__device__ float g_selbox[N_IMG * PRE * 4];       // top-3000 boxes
__device__ int   g_selfin[N_IMG * PRE];           // finite-score flag
__device__ unsigned g_mask[N_IMG * PRE * NWORDS]; // iou>0.7 bitmask rows

__device__ __forceinline__ float read_scalar(const int* p) {
    int iv = *p;
    if (iv > 0 && iv < (1 << 24)) return (float)iv;
    return *reinterpret_cast<const float*>(p);
}

union F2U { unsigned long long u; float2 f; };

#define FMA2(d, a, b) asm("fma.rn.f32x2 %0, %1, %2, %0;" : "+l"(d) : "l"(a), "l"(b))

// ===================== pre-conv kernels (conv must be 4th launch for ncu) =====================
__global__ void anchors_kernel(float* __restrict__ anch_out)
{
    int li = blockIdx.x * blockDim.x + threadIdx.x;
    if (li >= NANCH) return;
    int pix = li / 9;
    int a = li - pix * 9;
    int y = pix >> 6, x = pix & 63;
    int ri = a / 3, si = a - ri * 3;
    float ratio = (ri == 0) ? 0.5f : ((ri == 1) ? 1.0f : 2.0f);
    float scl = (si == 0) ? 8.f : ((si == 1) ? 16.f : 32.f);
    float hs = (16.f * scl) * sqrtf(ratio);
    float ws = (16.f * scl) * sqrtf(1.0f / ratio);
    float sy = (float)(y * 16), sx = (float)(x * 16);
    float* ap = anch_out + (size_t)li * 4;
    ap[0] = sy + (8.f - hs * 0.5f);
    ap[1] = sx + (8.f - ws * 0.5f);
    ap[2] = sy + (8.f + hs * 0.5f);
    ap[3] = sx + (8.f + ws * 0.5f);
}

__global__ void pad_keys_kernel()
{
    int t = blockIdx.x * blockDim.x + threadIdx.x;
    int per = NS - NANCH;               // 28672
    if (t >= N_IMG * per) return;
    int img = t / per, li = NANCH + (t - img * per);
    g_keys[(size_t)img * NS + li] = 0xFFFFFFFFFFFFFFFFull;
}

// W1[m][c*9+r]  ->  g_wt[(r*512+c)*512 + m]
__global__ void wtrans_kernel(const float* __restrict__ W1)
{
    int t = blockIdx.x * blockDim.x + threadIdx.x;
    if (t >= KTOT * C_IN) return;
    int k = t >> 9, m = t & 511;
    int rr = k >> 9, c = k & 511;
    g_wt[t] = W1[(size_t)m * KTOT + c * 9 + rr];
}

// ===================== conv 3x3, 512->512, pad 1, + bias + relu =====================
// implicit GEMM, K reordered: k = r*512 + c  (r = spatial tap, outer; c = channel, inner)
// tile 128x128, 256 threads, thread tile 8m x 8n as 32 f32x2 accumulators
__global__ __launch_bounds__(256, 2) void conv3x3_kernel(
    const float* __restrict__ x, const float* __restrict__ bias)
{
    __shared__ float Asd[2][8][256];   // A duplicated pairs: [kk][2m]=[kk][2m+1]=W[m]
    __shared__ float Bs[2][8][128];

    const int tid = threadIdx.x;
    const int n0 = blockIdx.x * 128;
    const int m0 = blockIdx.y * 128;

    // ---- B (im2col) per-thread slots: 4 values per K-step ----
    // slot i: idx = tid + i*256; bks = channel offset 0..7; bn = col 0..127
    int by[4], bx[4];
    const float* xb[4];               // x + img*C_IN*SP + bks*SP
    float* bst[4];                    // &Bs[0][bks][bn]
    int off[4]; bool pred[4];
#pragma unroll
    for (int i = 0; i < 4; i++) {
        int idx = tid + i * 256;
        int bks = idx >> 7;
        int bn = idx & 127;
        int col = n0 + bn;
        int img = col >> 12;
        by[i] = (col >> 6) & 63;
        bx[i] = col & 63;
        xb[i] = x + (size_t)img * (C_IN * SP) + (size_t)bks * SP;
        bst[i] = &Bs[0][bks][bn];
    }

#define SETOFF(RR) do { \
    int ky = (RR) / 3, kx = (RR) - 3 * (ky); \
    _Pragma("unroll") \
    for (int i = 0; i < 4; i++) { \
        int yy = by[i] + ky - 1, xx = bx[i] + kx - 1; \
        pred[i] = ((unsigned)yy < 64u) && ((unsigned)xx < 64u); \
        off[i] = (yy << 6) + xx; \
    } } while (0)

    // ---- A fill: thread loads float4 of g_wt row (k = s*8+kq), cols m0+mm..+3 ----
    const int kq = tid >> 5;            // 0..7
    const int mm = (tid & 31) * 4;      // 0..124
    const float* Aptr = g_wt + (size_t)kq * C_IN + m0 + mm;

    unsigned long long acc[8][4];
#pragma unroll
    for (int mi = 0; mi < 8; mi++)
#pragma unroll
        for (int ni = 0; ni < 4; ni++) acc[mi][ni] = 0ull;

    const int tm = tid >> 4;            // 0..15
    const int tn = tid & 15;            // 0..15

    float4 aw;
    float bv[4];

#define LOAD_B(C0E) do { \
    _Pragma("unroll") \
    for (int i = 0; i < 4; i++) \
        bv[i] = pred[i] ? __ldg(xb[i] + (C0E) + off[i]) : 0.f; \
    } while (0)

#define STS_AB(BUF) do { \
    float* ad = &Asd[BUF][kq][2 * mm]; \
    _Pragma("unroll") \
    for (int j = 0; j < 4; j++) { \
        float v = (&aw.x)[j]; \
        *reinterpret_cast<float2*>(ad + 2 * j) = make_float2(v, v); \
    } \
    _Pragma("unroll") \
    for (int i = 0; i < 4; i++) bst[i][(BUF) * (8 * 128)] = bv[i]; \
    } while (0)

    SETOFF(0);
    aw = *reinterpret_cast<const float4*>(Aptr);
    LOAD_B(0);
    STS_AB(0);
    __syncthreads();

    int buf = 0;
    for (int s = 0; s < 576; s++) {
        const bool more = s < 575;
        if (more) {
            Aptr += 8 * C_IN;
            aw = *reinterpret_cast<const float4*>(Aptr);
            int sn = s + 1;
            if ((sn & 63) == 0) SETOFF(sn >> 6);
            LOAD_B((sn & 63) << 15);
        }

#pragma unroll
        for (int kk = 0; kk < 8; kk++) {
            const unsigned long long* Bp =
                reinterpret_cast<const unsigned long long*>(&Bs[buf][kk][tn * 8]);
            unsigned long long b0 = Bp[0], b1 = Bp[1], b2 = Bp[2], b3 = Bp[3];
            const unsigned long long* Ap =
                reinterpret_cast<const unsigned long long*>(&Asd[buf][kk][0]) + tm * 8;
#pragma unroll
            for (int mi = 0; mi < 8; mi++) {
                unsigned long long a = Ap[mi];
                FMA2(acc[mi][0], a, b0);
                FMA2(acc[mi][1], a, b1);
                FMA2(acc[mi][2], a, b2);
                FMA2(acc[mi][3], a, b3);
            }
        }

        if (more) STS_AB(buf ^ 1);
        __syncthreads();
        buf ^= 1;
    }

    const int colbase = n0 + tn * 8;
    const int img = colbase >> 12;
    const int spbase = colbase & 4095;
#pragma unroll
    for (int mi = 0; mi < 8; mi++) {
        int m = m0 + tm * 8 + mi;
        float bvv = bias[m];
        float* hp = g_h + ((size_t)img * C_IN + m) * SP + spbase;
#pragma unroll
        for (int ni = 0; ni < 4; ni++) {
            F2U u; u.u = acc[mi][ni];
            float2 v;
            v.x = fmaxf(u.f.x + bvv, 0.f);
            v.y = fmaxf(u.f.y + bvv, 0.f);
            *reinterpret_cast<float2*>(hp + ni * 2) = v;
        }
    }
}

// ===================== heads: 1x1 convs (18 score, 36 loc), transpose, softmax =====================
__global__ __launch_bounds__(128) void heads_kernel(
    const float* __restrict__ Ws, const float* __restrict__ bs,
    const float* __restrict__ Wl, const float* __restrict__ bl,
    float* __restrict__ out)
{
    __shared__ float Wt[54][64];
    const int tid = threadIdx.x;
    const int col = blockIdx.x * 128 + tid;
    const int img = col >> 12;
    const int sp = col & 4095;

    float acc[54];
#pragma unroll
    for (int o = 0; o < 54; o++) acc[o] = 0.f;

    for (int c0 = 0; c0 < C_IN; c0 += 64) {
        for (int i = tid; i < 54 * 64; i += 128) {
            int o = i >> 6, cc = i & 63;
            Wt[o][cc] = (o < 18) ? Ws[o * C_IN + c0 + cc] : Wl[(o - 18) * C_IN + c0 + cc];
        }
        __syncthreads();
        const float* hp = g_h + (size_t)img * C_IN * SP + (size_t)c0 * SP + sp;
#pragma unroll 4
        for (int cc = 0; cc < 64; cc++) {
            float xv = hp[(size_t)cc * SP];
#pragma unroll
            for (int o = 0; o < 54; o++) acc[o] += xv * Wt[o][cc];
        }
        __syncthreads();
    }

    const size_t base9 = (size_t)img * NANCH + (size_t)sp * 9;
#pragma unroll
    for (int o = 0; o < 18; o++) {
        float v = acc[o] + bs[o];
        out[OFF_SC + (base9 + (o >> 1)) * 2 + (o & 1)] = v;
    }
#pragma unroll
    for (int o = 0; o < 36; o++) {
        float v = acc[18 + o] + bl[o];
        out[OFF_LOC + (base9 + (o >> 2)) * 4 + (o & 3)] = v;
    }
#pragma unroll
    for (int a = 0; a < 9; a++) {
        float s0 = acc[2 * a] + bs[2 * a];
        float s1 = acc[2 * a + 1] + bs[2 * a + 1];
        float m = fmaxf(s0, s1);
        float e0 = expf(s0 - m), e1 = expf(s1 - m);
        g_fg[base9 + a] = e1 / (e0 + e1);
    }
}

// ===================== loc2bbox + clip + min-size + sort keys =====================
__global__ void boxes_kernel(const float* __restrict__ locs,
                             const int* __restrict__ imh_p, const int* __restrict__ imw_p)
{
    int t = blockIdx.x * blockDim.x + threadIdx.x;
    if (t >= N_IMG * NANCH) return;
    int img = t / NANCH;
    int li = t - img * NANCH;

    int pix = li / 9;
    int a = li - pix * 9;
    int y = pix >> 6, x = pix & 63;
    int ri = a / 3, si = a - ri * 3;
    float ratio = (ri == 0) ? 0.5f : ((ri == 1) ? 1.0f : 2.0f);
    float scl = (si == 0) ? 8.f : ((si == 1) ? 16.f : 32.f);
    float hs = (16.f * scl) * sqrtf(ratio);
    float ws = (16.f * scl) * sqrtf(1.0f / ratio);
    float sy = (float)(y * 16), sx = (float)(x * 16);
    float ay1 = sy + (8.f - hs * 0.5f);
    float ax1 = sx + (8.f - ws * 0.5f);
    float ay2 = sy + (8.f + hs * 0.5f);
    float ax2 = sx + (8.f + ws * 0.5f);

    const float* lp = locs + ((size_t)img * NANCH + li) * 4;
    float dy = lp[0], dx = lp[1], dh = lp[2], dw = lp[3];
    float ah = ay2 - ay1, aw = ax2 - ax1;
    float acy = ay1 + 0.5f * ah, acx = ax1 + 0.5f * aw;
    float cy = dy * ah + acy, cx = dx * aw + acx;
    float hb = expf(dh) * ah, wb = expf(dw) * aw;

    float imh = read_scalar(imh_p);
    float imw = read_scalar(imw_p);
    float y1 = fminf(fmaxf(cy - 0.5f * hb, 0.f), imh);
    float x1 = fminf(fmaxf(cx - 0.5f * wb, 0.f), imw);
    float y2 = fminf(fmaxf(cy + 0.5f * hb, 0.f), imh);
    float x2 = fminf(fmaxf(cx + 0.5f * wb, 0.f), imw);

    float* bp = g_boxes + ((size_t)img * NANCH + li) * 4;
    bp[0] = y1; bp[1] = x1; bp[2] = y2; bp[3] = x2;

    bool valid = ((y2 - y1) >= 16.f) && ((x2 - x1) >= 16.f);
    float s = valid ? g_fg[(size_t)img * NANCH + li] : -INFINITY;
    unsigned u = __float_as_uint(s);
    unsigned desc = (u & 0x80000000u) ? u : (~u & 0x7FFFFFFFu);   // ascending key = descending score
    g_keys[(size_t)img * NS + li] = ((unsigned long long)desc << 32) | (unsigned)li;
}

// ===================== bitonic sort (per-image 65536 keys, ascending) =====================
__global__ __launch_bounds__(512) void sort_local8k()
{
    extern __shared__ unsigned long long s[];
    const int base = blockIdx.x * 8192;
    for (int i = threadIdx.x; i < 8192; i += 512) s[i] = g_keys[base + i];
    __syncthreads();
    for (int k = 2; k <= 8192; k <<= 1) {
        for (int j = k >> 1; j > 0; j >>= 1) {
            for (int t = threadIdx.x; t < 4096; t += 512) {
                int i = ((t & ~(j - 1)) << 1) | (t & (j - 1));
                int l = i | j;
                bool up = (((base + i) & k) == 0);
                unsigned long long va = s[i], vb = s[l];
                if ((va > vb) == up) { s[i] = vb; s[l] = va; }
            }
            __syncthreads();
        }
    }
    for (int i = threadIdx.x; i < 8192; i += 512) g_keys[base + i] = s[i];
}

__global__ void sort_global(int k, int j)
{
    int t = blockIdx.x * blockDim.x + threadIdx.x;  // 4*32768
    int img = t >> 15, tt = t & 32767;
    int i = ((tt & ~(j - 1)) << 1) | (tt & (j - 1));
    int l = i | j;
    unsigned long long* p = g_keys + (size_t)img * NS;
    bool up = ((i & k) == 0);
    unsigned long long va = p[i], vb = p[l];
    if ((va > vb) == up) { p[i] = vb; p[l] = va; }
}

__global__ __launch_bounds__(512) void merge_local8k(int k)
{
    extern __shared__ unsigned long long s[];
    const int base = blockIdx.x * 8192;
    for (int i = threadIdx.x; i < 8192; i += 512) s[i] = g_keys[base + i];
    __syncthreads();
    bool up = (((base & (NS - 1)) & k) == 0);
    for (int j = 4096; j > 0; j >>= 1) {
        for (int t = threadIdx.x; t < 4096; t += 512) {
            int i = ((t & ~(j - 1)) << 1) | (t & (j - 1));
            int l = i | j;
            unsigned long long va = s[i], vb = s[l];
            if ((va > vb) == up) { s[i] = vb; s[l] = va; }
        }
        __syncthreads();
    }
    for (int i = threadIdx.x; i < 8192; i += 512) g_keys[base + i] = s[i];
}

// ===================== gather top-3000 =====================
__global__ void gather_kernel()
{
    int t = blockIdx.x * blockDim.x + threadIdx.x;
    if (t >= N_IMG * PRE) return;
    int img = t / PRE, r = t - img * PRE;
    unsigned long long key = g_keys[(size_t)img * NS + r];
    int li = (int)(key & 0xFFFFFFFFull);
    unsigned desc = (unsigned)(key >> 32);
    g_selfin[img * PRE + r] = (desc < 0xFF800000u) ? 1 : 0;  // finite score
    float4 b = *reinterpret_cast<const float4*>(&g_boxes[((size_t)img * NANCH + li) * 4]);
    *reinterpret_cast<float4*>(&g_selbox[((size_t)img * PRE + r) * 4]) = b;
}

// ===================== IoU > 0.7 bitmask =====================
__global__ void iou_kernel()
{
    int t = blockIdx.x * blockDim.x + threadIdx.x;
    if (t >= N_IMG * PRE * NWORDS) return;
    int img = t / (PRE * NWORDS);
    int rem = t - img * (PRE * NWORDS);
    int i = rem / NWORDS;
    int w = rem - i * NWORDS;
    const float* B = g_selbox + (size_t)img * PRE * 4;
    float4 bi = *reinterpret_cast<const float4*>(B + (size_t)i * 4);
    float ai = (bi.z - bi.x) * (bi.w - bi.y);
    unsigned bits = 0;
    int j0 = w * 32;
#pragma unroll 4
    for (int jj = 0; jj < 32; jj++) {
        int j = j0 + jj;
        if (j >= PRE) break;
        float4 bj = *reinterpret_cast<const float4*>(B + (size_t)j * 4);
        float yy1 = fmaxf(bi.x, bj.x), xx1 = fmaxf(bi.y, bj.y);
        float yy2 = fminf(bi.z, bj.z), xx2 = fminf(bi.w, bj.w);
        float ih = fmaxf(yy2 - yy1, 0.f), iw = fmaxf(xx2 - xx1, 0.f);
        float inter = ih * iw;
        float aj = (bj.z - bj.x) * (bj.w - bj.y);
        float uni = ai + aj - inter;
        float iou = (uni > 0.f) ? (inter / uni) : 0.f;
        if (iou > 0.7f) bits |= (1u << jj);
    }
    g_mask[((size_t)img * PRE + i) * NWORDS + w] = bits;
}

// ===================== sequential greedy NMS with 8-deep row prefetch =====================
__global__ void nms_kernel(float* __restrict__ out)
{
    const int img = blockIdx.x;
    const int lane = threadIdx.x;
    __shared__ int kept[POST];
    __shared__ int s_nk;
    unsigned r0 = 0, r1 = 0, r2 = 0;   // lane owns removed-words [3*lane .. 3*lane+2]
    int nk = 0;
    const unsigned* M = g_mask + (size_t)img * PRE * NWORDS;
    const int* fin = g_selfin + img * PRE;
    const int b0 = lane * 3;
    const bool v0 = (b0 < NWORDS), v1 = (b0 + 1 < NWORDS), v2 = (b0 + 2 < NWORDS);

    unsigned p0[8], p1[8], p2[8];      // prefetched rows i..i+7
#pragma unroll
    for (int s = 0; s < 8; s++) {
        const unsigned* row = M + (size_t)s * NWORDS + b0;
        p0[s] = v0 ? __ldg(row) : 0u;
        p1[s] = v1 ? __ldg(row + 1) : 0u;
        p2[s] = v2 ? __ldg(row + 2) : 0u;
    }

    for (int ib = 0; ib < PRE; ib += 8) {
#pragma unroll
        for (int s = 0; s < 8; s++) {
            int i = ib + s;
            int wi = i >> 5;
            int owner = wi / 3, sub = wi - owner * 3;
            unsigned myw = (sub == 0) ? r0 : ((sub == 1) ? r1 : r2);
            unsigned word = __shfl_sync(0xffffffffu, myw, owner);
            if (!((word >> (i & 31)) & 1u)) {
                if (lane == 0 && fin[i] && nk < POST) { kept[nk] = i; nk++; }
                r0 |= p0[s]; r1 |= p1[s]; r2 |= p2[s];
            }
            int ip = i + 8;
            if (ip < PRE) {
                const unsigned* row = M + (size_t)ip * NWORDS + b0;
                p0[s] = v0 ? __ldg(row) : 0u;
                p1[s] = v1 ? __ldg(row + 1) : 0u;
                p2[s] = v2 ? __ldg(row + 2) : 0u;
            }
        }
        int cnt = __shfl_sync(0xffffffffu, nk, 0);
        if (cnt >= POST) break;
    }
    if (lane == 0) s_nk = nk;
    __syncwarp();
    int NK = s_nk;

    for (int r = lane; r < POST; r += 32) {
        float4 b = make_float4(0.f, 0.f, 0.f, 0.f);
        float v = 0.f;
        if (r < NK) {
            b = *reinterpret_cast<const float4*>(&g_selbox[((size_t)img * PRE + kept[r]) * 4]);
            v = 1.f;
        }
        float* rp = out + OFF_ROI + ((size_t)img * POST + r) * 4;
        rp[0] = b.x; rp[1] = b.y; rp[2] = b.z; rp[3] = b.w;
        out[OFF_VAL + img * POST + r] = v;
    }
}

// ===================== launch =====================
extern "C" void kernel_launch(void* const* d_in, const int* in_sizes, int n_in,
                              void* d_out, int out_size)
{
    const float* x  = (const float*)d_in[0];
    const float* W1 = (const float*)d_in[1];
    const float* b1 = (const float*)d_in[2];
    const float* Ws = (const float*)d_in[3];
    const float* bs = (const float*)d_in[4];
    const float* Wl = (const float*)d_in[5];
    const float* bl = (const float*)d_in[6];
    const int* imh  = (const int*)d_in[7];
    const int* imw  = (const int*)d_in[8];
    float* out = (float*)d_out;

    cudaFuncSetAttribute(sort_local8k, cudaFuncAttributeMaxDynamicSharedMemorySize, 65536);
    cudaFuncSetAttribute(merge_local8k, cudaFuncAttributeMaxDynamicSharedMemorySize, 65536);

    // conv is the 4th launch (empirically the one ncu profiles)
    anchors_kernel<<<(NANCH + 255) / 256, 256>>>(out + OFF_ANC);
    pad_keys_kernel<<<(N_IMG * (NS - NANCH) + 255) / 256, 256>>>();
    wtrans_kernel<<<(KTOT * C_IN + 255) / 256, 256>>>(W1);

    conv3x3_kernel<<<dim3(128, 4), 256>>>(x, b1);
    heads_kernel<<<128, 128>>>(Ws, bs, Wl, bl, out);
    boxes_kernel<<<(N_IMG * NANCH + 255) / 256, 256>>>(out + OFF_LOC, imh, imw);

    sort_local8k<<<32, 512, 65536>>>();
    for (int k = 16384; k <= 65536; k <<= 1) {
        for (int j = k >> 1; j >= 8192; j >>= 1)
            sort_global<<<512, 256>>>(k, j);
        merge_local8k<<<32, 512, 65536>>>(k);
    }

    gather_kernel<<<(N_IMG * PRE + 255) / 256, 256>>>();
    iou_kernel<<<(N_IMG * PRE * NWORDS + 255) / 256, 256>>>();
    nms_kernel<<<4, 32>>>(out);
}